// round 2
// baseline (speedup 1.0000x reference)
#include <cuda_runtime.h>
#include <math.h>
#include <stdint.h>

#define BATCH 65536
#define NQ    256

// ---------------- scratch (device globals; no dynamic allocation) ----------------
__device__ float g_bufA[BATCH * NQ];
__device__ float g_bufB[BATCH * NQ];
__device__ float g_h   [BATCH * 768];
__device__ float g_t2  [BATCH * NQ];
__device__ float g_t3  [BATCH * NQ];
__device__ float g_entT[8 * NQ * NQ];
__device__ float g_lin [8 * NQ];

// ---------------- precompute: tanh(ent) and lin per (layer, col) ----------------
__global__ void precompute_kernel(const float* __restrict__ ent,
                                  const float* __restrict__ gp) {
    int i = blockIdx.x * blockDim.x + threadIdx.x;
    const int total = 8 * NQ * NQ;
    if (i < total) g_entT[i] = tanhf(ent[i]);
    if (i < 8 * NQ) {
        const float* p = gp + (size_t)i * 6;
        g_lin[i] = sinf(p[0]) + cosf(p[1]) + tanhf(p[2]);
    }
}

// ---------------- GEMM: C[B x N] = epi(A[B x K] @ W[K x N] + bias) ----------------
// EPI: 0=bias only, 1=silu, 2=tanh, 3=gate+entangle combine, 4=nl residual (aux + 0.1*v)
template <int EPI>
__global__ __launch_bounds__(256) void gemm_kernel(
    const float* __restrict__ A, const float* __restrict__ W, int ldw,
    const float* __restrict__ bias, float* __restrict__ out,
    const float* __restrict__ aux, const float* __restrict__ gp,
    const float* __restrict__ lin, int K, int N)
{
    __shared__ float As[16][132];   // padded to reduce STS conflicts; 132*4B keeps 16B alignment
    __shared__ float Ws[16][64];

    const int tid = threadIdx.x;
    const int m0 = blockIdx.y * 128;
    const int n0 = blockIdx.x * 64;
    const int ty = tid >> 4;        // 0..15 -> 8 rows each
    const int tx = tid & 15;        // 0..15 -> 4 cols each

    float acc[8][4];
#pragma unroll
    for (int i = 0; i < 8; i++)
#pragma unroll
        for (int j = 0; j < 4; j++) acc[i][j] = 0.f;

    for (int k0 = 0; k0 < K; k0 += 16) {
        // load A tile: 128 rows x 16 cols (512 float4)
#pragma unroll
        for (int it = 0; it < 2; it++) {
            int t   = tid + it * 256;
            int row = t >> 2;
            int kq  = t & 3;
            float4 v = *(const float4*)(A + (size_t)(m0 + row) * K + k0 + kq * 4);
            As[kq * 4 + 0][row] = v.x;
            As[kq * 4 + 1][row] = v.y;
            As[kq * 4 + 2][row] = v.z;
            As[kq * 4 + 3][row] = v.w;
        }
        // load W tile: 16 rows x 64 cols (256 float4), one per thread
        {
            int row = tid >> 4;
            int nq  = tid & 15;
            float4 v = *(const float4*)(W + (size_t)(k0 + row) * ldw + n0 + nq * 4);
            *(float4*)&Ws[row][nq * 4] = v;
        }
        __syncthreads();

#pragma unroll
        for (int k = 0; k < 16; k++) {
            float4 a0 = *(float4*)&As[k][ty * 8];
            float4 a1 = *(float4*)&As[k][ty * 8 + 4];
            float4 w4 = *(float4*)&Ws[k][tx * 4];
            float a[8] = {a0.x, a0.y, a0.z, a0.w, a1.x, a1.y, a1.z, a1.w};
            float w[4] = {w4.x, w4.y, w4.z, w4.w};
#pragma unroll
            for (int i = 0; i < 8; i++)
#pragma unroll
                for (int j = 0; j < 4; j++) acc[i][j] += a[i] * w[j];
        }
        __syncthreads();
    }

    // ---- epilogue ----
    float bv[4] = {0.f, 0.f, 0.f, 0.f};
    if (bias != nullptr) {
#pragma unroll
        for (int j = 0; j < 4; j++) bv[j] = bias[n0 + tx * 4 + j];
    }

    float linv[4], p3v[4], p4v[4], p5v[4];
    if (EPI == 3) {
#pragma unroll
        for (int j = 0; j < 4; j++) {
            int n = n0 + tx * 4 + j;
            linv[j] = lin[n];
            p3v[j]  = gp[(size_t)n * 6 + 3];
            p4v[j]  = gp[(size_t)n * 6 + 4];
            p5v[j]  = gp[(size_t)n * 6 + 5];
        }
    }

#pragma unroll
    for (int i = 0; i < 8; i++) {
        int m = m0 + ty * 8 + i;
        float ov[4];
#pragma unroll
        for (int j = 0; j < 4; j++) {
            float v = acc[i][j] + bv[j];
            int n = n0 + tx * 4 + j;
            if (EPI == 0) {
                ov[j] = v;
            } else if (EPI == 1) {          // silu
                ov[j] = v / (1.f + expf(-v));
            } else if (EPI == 2) {          // tanh
                ov[j] = tanhf(v);
            } else if (EPI == 3) {          // gate + entangle combine
                float c = aux[(size_t)m * N + n];
                float gate = 0.25f * (linv[j] * c
                                      + 0.5f * sinf(p3v[j] * c + p4v[j])
                                      + 0.5f * cosf(p5v[j] * c));
                ov[j] = (c + 0.3f * gate + 0.2f * v) * (1.f / 1.5f);
            } else {                        // EPI == 4: nl residual
                ov[j] = aux[(size_t)m * N + n] + 0.1f * v;
            }
        }
        float4 o4 = make_float4(ov[0], ov[1], ov[2], ov[3]);
        *(float4*)(out + (size_t)m * N + n0 + tx * 4) = o4;
    }
}

// ---------------- LayerNorm(768) + exact GELU, in place ----------------
__global__ __launch_bounds__(256) void lngelu_kernel(float* __restrict__ h,
                                                     const float* __restrict__ w,
                                                     const float* __restrict__ b) {
    __shared__ float red[8];
    __shared__ float bc;
    const int row = blockIdx.x;
    const int tid = threadIdx.x;
    float* hr = h + (size_t)row * 768;

    float v[3];
    v[0] = hr[tid];
    v[1] = hr[tid + 256];
    v[2] = hr[tid + 512];

    // sum -> mean
    float s = v[0] + v[1] + v[2];
    {
        int lane = tid & 31, wid = tid >> 5;
#pragma unroll
        for (int o = 16; o > 0; o >>= 1) s += __shfl_xor_sync(0xffffffffu, s, o);
        if (lane == 0) red[wid] = s;
        __syncthreads();
        if (tid < 8) {
            float t = red[tid];
#pragma unroll
            for (int o = 4; o > 0; o >>= 1) t += __shfl_xor_sync(0xffu, t, o);
            if (tid == 0) bc = t;
        }
        __syncthreads();
    }
    float mu = bc * (1.f / 768.f);
    __syncthreads();

    // var
    float d0 = v[0] - mu, d1 = v[1] - mu, d2 = v[2] - mu;
    float ss = d0 * d0 + d1 * d1 + d2 * d2;
    {
        int lane = tid & 31, wid = tid >> 5;
#pragma unroll
        for (int o = 16; o > 0; o >>= 1) ss += __shfl_xor_sync(0xffffffffu, ss, o);
        if (lane == 0) red[wid] = ss;
        __syncthreads();
        if (tid < 8) {
            float t = red[tid];
#pragma unroll
            for (int o = 4; o > 0; o >>= 1) t += __shfl_xor_sync(0xffu, t, o);
            if (tid == 0) bc = t;
        }
        __syncthreads();
    }
    float var = bc * (1.f / 768.f);
    float inv = rsqrtf(var + 1e-5f);

#pragma unroll
    for (int e = 0; e < 3; e++) {
        int c = tid + e * 256;
        float o = (v[e] - mu) * inv * w[c] + b[c];
        hr[c] = 0.5f * o * (1.f + erff(o * 0.70710678118654752f));
    }
}

// ---------------- residual mix + L2 normalize + tanh (warp per row) ----------------
__global__ __launch_bounds__(256) void mix_kernel(const float* __restrict__ c3,
                                                  const float* __restrict__ res,
                                                  float* __restrict__ out, float alpha) {
    const int warp = threadIdx.x >> 5;
    const int lane = threadIdx.x & 31;
    const int row  = blockIdx.x * 8 + warp;
    const float beta = 1.f - alpha;

    const float4* c4 = (const float4*)(c3  + (size_t)row * NQ);
    const float4* r4 = (const float4*)(res + (size_t)row * NQ);

    float4 m[2];
    float ss = 0.f;
#pragma unroll
    for (int t = 0; t < 2; t++) {
        int idx = lane + t * 32;
        float4 a = c4[idx];
        float4 b = r4[idx];
        float4 mm;
        mm.x = alpha * a.x + beta * b.x;
        mm.y = alpha * a.y + beta * b.y;
        mm.z = alpha * a.z + beta * b.z;
        mm.w = alpha * a.w + beta * b.w;
        ss += mm.x * mm.x + mm.y * mm.y + mm.z * mm.z + mm.w * mm.w;
        m[t] = mm;
    }
#pragma unroll
    for (int o = 16; o > 0; o >>= 1) ss += __shfl_xor_sync(0xffffffffu, ss, o);
    float inv = 1.f / (sqrtf(ss) + 1e-8f);

    float4* o4 = (float4*)(out + (size_t)row * NQ);
#pragma unroll
    for (int t = 0; t < 2; t++) {
        int idx = lane + t * 32;
        float4 mm = m[t];
        float4 oo;
        oo.x = tanhf(mm.x * inv);
        oo.y = tanhf(mm.y * inv);
        oo.z = tanhf(mm.z * inv);
        oo.w = tanhf(mm.w * inv);
        o4[idx] = oo;
    }
}

// ---------------- host orchestration ----------------
static void launch_gemm(int epi, const float* A, const float* W, int ldw,
                        const float* bias, float* out, const float* aux,
                        const float* gp, const float* lin, int K, int N) {
    dim3 grid(N / 64, BATCH / 128);
    switch (epi) {
        case 0: gemm_kernel<0><<<grid, 256>>>(A, W, ldw, bias, out, aux, gp, lin, K, N); break;
        case 1: gemm_kernel<1><<<grid, 256>>>(A, W, ldw, bias, out, aux, gp, lin, K, N); break;
        case 2: gemm_kernel<2><<<grid, 256>>>(A, W, ldw, bias, out, aux, gp, lin, K, N); break;
        case 3: gemm_kernel<3><<<grid, 256>>>(A, W, ldw, bias, out, aux, gp, lin, K, N); break;
        default: gemm_kernel<4><<<grid, 256>>>(A, W, ldw, bias, out, aux, gp, lin, K, N); break;
    }
}

extern "C" void kernel_launch(void* const* d_in, const int* in_sizes, int n_in,
                              void* d_out, int out_size) {
    const float* x     = (const float*)d_in[0];
    const float* d0w1  = (const float*)d_in[1];
    const float* d0b1  = (const float*)d_in[2];
    const float* lnw   = (const float*)d_in[3];
    const float* lnb   = (const float*)d_in[4];
    const float* d0w2  = (const float*)d_in[5];
    const float* d0b2  = (const float*)d_in[6];
    const float* d1w1  = (const float*)d_in[7];
    const float* d1b1  = (const float*)d_in[8];
    const float* d1w2  = (const float*)d_in[9];
    const float* d1b2  = (const float*)d_in[10];
    const float* awqkv = (const float*)d_in[11];
    const float* abqkv = (const float*)d_in[12];
    const float* awo   = (const float*)d_in[13];
    const float* abo   = (const float*)d_in[14];
    const float* gp    = (const float*)d_in[15];
    const float* ent   = (const float*)d_in[16];
    const float* nlw1  = (const float*)d_in[17];
    const float* nlb1  = (const float*)d_in[18];
    const float* nlw2  = (const float*)d_in[19];
    const float* nlb2  = (const float*)d_in[20];

    float *bufA, *bufB, *h, *t2, *t3, *entT, *lin;
    cudaGetSymbolAddress((void**)&bufA, g_bufA);
    cudaGetSymbolAddress((void**)&bufB, g_bufB);
    cudaGetSymbolAddress((void**)&h,    g_h);
    cudaGetSymbolAddress((void**)&t2,   g_t2);
    cudaGetSymbolAddress((void**)&t3,   g_t3);
    cudaGetSymbolAddress((void**)&entT, g_entT);
    cudaGetSymbolAddress((void**)&lin,  g_lin);

    precompute_kernel<<<(8 * NQ * NQ + 255) / 256, 256>>>(ent, gp);

    const float* cur = x;
    for (int li = 0; li < 8; li++) {
        float* nxt = (li == 7) ? (float*)d_out : ((li & 1) ? bufB : bufA);
        int t = li % 3;
        if (t == 0) {
            int i = li / 3;
            launch_gemm(0, cur, d0w1 + (size_t)i * 256 * 768, 768,
                        d0b1 + (size_t)i * 768, h, nullptr, nullptr, nullptr, 256, 768);
            lngelu_kernel<<<BATCH, 256>>>(h, lnw + (size_t)i * 768, lnb + (size_t)i * 768);
            launch_gemm(0, h, d0w2 + (size_t)i * 768 * 256, 256,
                        d0b2 + (size_t)i * 256, t2, nullptr, nullptr, nullptr, 768, 256);
        } else if (t == 1) {
            int i = (li - 1) / 3;
            launch_gemm(1, cur, d1w1 + (size_t)i * 256 * 512, 512,
                        d1b1 + (size_t)i * 512, h, nullptr, nullptr, nullptr, 256, 512);
            launch_gemm(0, h, d1w2 + (size_t)i * 512 * 256, 256,
                        d1b2 + (size_t)i * 256, t2, nullptr, nullptr, nullptr, 512, 256);
        } else {
            int i = (li - 2) / 3;
            // only the V slice of wqkv matters: columns [512, 768)
            launch_gemm(0, cur, awqkv + (size_t)i * 256 * 768 + 512, 768,
                        abqkv + (size_t)i * 768 + 512, t3, nullptr, nullptr, nullptr, 256, 256);
            launch_gemm(0, t3, awo + (size_t)i * 256 * 256, 256,
                        abo + (size_t)i * 256, t2, nullptr, nullptr, nullptr, 256, 256);
        }

        // entangle GEMM with fused gate epilogue: t3 = combine(t2, t2 @ tanh(ent))
        launch_gemm(3, t2, entT + (size_t)li * 256 * 256, 256, nullptr, t3,
                    t2, gp + (size_t)li * 256 * 6, lin + (size_t)li * 256, 256, 256);

        float* c3 = t3;
        if (li & 1) {
            int j = li / 2;
            launch_gemm(2, t3, nlw1 + (size_t)j * 256 * 256, 256,
                        nlb1 + (size_t)j * 256, h, nullptr, nullptr, nullptr, 256, 256);
            launch_gemm(4, h, nlw2 + (size_t)j * 256 * 256, 256,
                        nlb2 + (size_t)j * 256, t2, t3, nullptr, nullptr, 256, 256);
            c3 = t2;
        }

        float alpha = (li < 4) ? 0.8f : 0.6f;
        mix_kernel<<<BATCH / 8, 256>>>(c3, cur, nxt, alpha);
        cur = nxt;
    }
}

// round 8
// speedup vs baseline: 1.4510x; 1.4510x over previous
#include <cuda_runtime.h>
#include <cuda_bf16.h>
#include <math.h>
#include <stdint.h>

#define BATCH 65536
#define NQ    256

typedef __nv_bfloat16  bf16;
typedef __nv_bfloat162 bf162;

// ======================= scratch (device globals) =======================
__device__ __align__(256) float g_bufA[BATCH * NQ];
__device__ __align__(256) float g_bufB[BATCH * NQ];
__device__ __align__(256) float g_h   [BATCH * 768];
__device__ __align__(256) float g_t2  [BATCH * NQ];
__device__ __align__(256) float g_t3  [BATCH * NQ];
__device__ __align__(256) float g_lin [8 * NQ];

__device__ __align__(256) bf16 g_xh [BATCH * NQ];
__device__ __align__(256) bf16 g_xl [BATCH * NQ];
__device__ __align__(256) bf16 g_Ah [BATCH * NQ];
__device__ __align__(256) bf16 g_Al [BATCH * NQ];
__device__ __align__(256) bf16 g_Bh2[BATCH * NQ];
__device__ __align__(256) bf16 g_Bl2[BATCH * NQ];
__device__ __align__(256) bf16 g_hh [BATCH * 768];
__device__ __align__(256) bf16 g_hl [BATCH * 768];
__device__ __align__(256) bf16 g_t2h[BATCH * NQ];
__device__ __align__(256) bf16 g_t2l[BATCH * NQ];
__device__ __align__(256) bf16 g_t3h[BATCH * NQ];
__device__ __align__(256) bf16 g_t3l[BATCH * NQ];

#define WTOT 3276800
__device__ __align__(256) bf16 g_wh[WTOT];
__device__ __align__(256) bf16 g_wl[WTOT];

// ======================= helpers =======================
__device__ __forceinline__ uint32_t smem_u32(const void* p) {
    uint32_t a;
    asm("{ .reg .u64 t; cvta.to.shared.u64 t, %1; cvt.u32.u64 %0, t; }" : "=r"(a) : "l"(p));
    return a;
}

#define CP_ASYNC16(dst, src) \
    asm volatile("cp.async.cg.shared.global [%0], [%1], 16;" :: "r"(dst), "l"(src) : "memory")
#define CP_COMMIT() asm volatile("cp.async.commit_group;" ::: "memory")
#define CP_WAIT2()  asm volatile("cp.async.wait_group 2;" ::: "memory")

#define LDSM4(r0, r1, r2, r3, addr) \
    asm volatile("ldmatrix.sync.aligned.m8n8.x4.shared.b16 {%0,%1,%2,%3}, [%4];" \
        : "=r"(r0), "=r"(r1), "=r"(r2), "=r"(r3) : "r"(addr))

__device__ __forceinline__ void mma_bf16(float* d, const uint32_t* a, const uint32_t* b) {
    asm volatile(
        "mma.sync.aligned.m16n8k16.row.col.f32.bf16.bf16.f32 "
        "{%0,%1,%2,%3}, {%4,%5,%6,%7}, {%8,%9}, {%0,%1,%2,%3};"
        : "+f"(d[0]), "+f"(d[1]), "+f"(d[2]), "+f"(d[3])
        : "r"(a[0]), "r"(a[1]), "r"(a[2]), "r"(a[3]), "r"(b[0]), "r"(b[1]));
}

__device__ __forceinline__ bf162 split_hi2(float a, float b, bf162& lo) {
    bf16 ha = __float2bfloat16(a);
    bf16 hb = __float2bfloat16(b);
    bf16 la = __float2bfloat16(a - __bfloat162float(ha));
    bf16 lb = __float2bfloat16(b - __bfloat162float(hb));
    lo = __halves2bfloat162(la, lb);
    return __halves2bfloat162(ha, hb);
}

// ======================= smem layout =======================
// per stage: Ah[128x40h] Al Bh Bl, each 10240 B; pitch 80 B (LDSM conflict-free)
#define MAT_BYTES   10240
#define STAGE_BYTES 40960
#define STAGES      4
#define SMEM_BYTES  (STAGES * STAGE_BYTES)

// ======================= mma.sync GEMM =======================
// C[B x N] = epi(A @ W^T + bias); A hi/lo bf16 [B x K]; W hi/lo bf16 [N x K].
template <int EPI, int WF32, int WSPLIT>
__global__ __launch_bounds__(256, 1) void gemm_mma(
    const bf16* __restrict__ Ah, const bf16* __restrict__ Al,
    const bf16* __restrict__ Bh, const bf16* __restrict__ Bl,
    const float* __restrict__ bias,
    float* __restrict__ outf, bf16* __restrict__ outh, bf16* __restrict__ outl,
    const float* __restrict__ aux, const float* __restrict__ gp,
    const float* __restrict__ lin, int K, int N)
{
    extern __shared__ char sm[];
    const uint32_t smem_base = smem_u32(sm);

    const int tid    = threadIdx.x;
    const int wid    = tid >> 5;
    const int lane   = tid & 31;
    const int warp_m = wid & 1;        // 2 warps over M: 64 rows each
    const int warp_n = wid >> 1;       // 4 warps over N: 32 cols each
    const int m0     = blockIdx.y * 128;
    const int n0     = blockIdx.x * 128;

    float acc[4][4][4];
#pragma unroll
    for (int a = 0; a < 4; a++)
#pragma unroll
        for (int b = 0; b < 4; b++)
#pragma unroll
            for (int c = 0; c < 4; c++) acc[a][b][c] = 0.f;

    const int nk = K >> 5;   // k-chunks of 32

    // ---- stage loader: 2048 x 16B chunks, 8 per thread ----
    auto load_stage = [&](int stage, int kblk) {
        const int k0 = kblk << 5;
        const uint32_t sb = smem_base + stage * STAGE_BYTES;
#pragma unroll
        for (int part = 0; part < 8; part++) {
            int id  = tid + part * 256;
            int mat = id >> 9;          // 0:Ah 1:Al 2:Bh 3:Bl
            int rem = id & 511;
            int row = rem >> 2;
            int ch  = rem & 3;
            const bf16* srcm = (mat == 0) ? Ah : (mat == 1) ? Al : (mat == 2) ? Bh : Bl;
            int grow = (mat < 2) ? (m0 + row) : (n0 + row);
            const bf16* s = srcm + (size_t)grow * K + k0 + ch * 8;
            uint32_t d = sb + mat * MAT_BYTES + row * 80 + ch * 16;
            CP_ASYNC16(d, s);
        }
    };

    // ---- prologue: stages 0..2 ----
    load_stage(0, 0); CP_COMMIT();
    load_stage(1, 1); CP_COMMIT();
    load_stage(2, 2); CP_COMMIT();

    const uint32_t a_lane_off = (warp_m * 64 + (lane & 15)) * 80 + ((lane >> 4) << 3) * 2;
    const uint32_t b_lane_off = (warp_n * 32 + (lane & 7) + ((lane >> 4) << 3)) * 80
                              + (((lane >> 3) & 1) << 3) * 2;

    for (int i = 0; i < nk; i++) {
        CP_WAIT2();
        __syncthreads();
        if (i + 3 < nk) load_stage((i + 3) & 3, i + 3);
        CP_COMMIT();

        const uint32_t sb = smem_base + (i & 3) * STAGE_BYTES;
#pragma unroll
        for (int kk = 0; kk < 2; kk++) {
            const uint32_t koff = (kk * 16) * 2;
            uint32_t af_h[4][4], af_l[4][4], bf_h[4][2], bf_l[4][2];
#pragma unroll
            for (int mt = 0; mt < 4; mt++) {
                uint32_t off = a_lane_off + mt * (16 * 80) + koff;
                LDSM4(af_h[mt][0], af_h[mt][1], af_h[mt][2], af_h[mt][3], sb + off);
                LDSM4(af_l[mt][0], af_l[mt][1], af_l[mt][2], af_l[mt][3], sb + MAT_BYTES + off);
            }
#pragma unroll
            for (int p = 0; p < 2; p++) {
                uint32_t off = b_lane_off + p * (16 * 80) + koff;
                LDSM4(bf_h[2 * p][0], bf_h[2 * p][1], bf_h[2 * p + 1][0], bf_h[2 * p + 1][1],
                      sb + 2 * MAT_BYTES + off);
                LDSM4(bf_l[2 * p][0], bf_l[2 * p][1], bf_l[2 * p + 1][0], bf_l[2 * p + 1][1],
                      sb + 3 * MAT_BYTES + off);
            }
#pragma unroll
            for (int mt = 0; mt < 4; mt++)
#pragma unroll
                for (int nt = 0; nt < 4; nt++) {
                    mma_bf16(acc[mt][nt], af_h[mt], bf_h[nt]);
                    mma_bf16(acc[mt][nt], af_l[mt], bf_h[nt]);
                    mma_bf16(acc[mt][nt], af_h[mt], bf_l[nt]);
                }
        }
    }

    // ---------- epilogue ----------
    const int l4 = lane >> 2;
    const int l2 = (lane & 3) * 2;

#pragma unroll
    for (int mt = 0; mt < 4; mt++) {
#pragma unroll
        for (int h = 0; h < 2; h++) {
            const int m = m0 + warp_m * 64 + mt * 16 + h * 8 + l4;
#pragma unroll
            for (int nt = 0; nt < 4; nt++) {
                const int n = n0 + warp_n * 32 + nt * 8 + l2;
                float vx = acc[mt][nt][2 * h];
                float vy = acc[mt][nt][2 * h + 1];

                if (EPI != 3) {
                    float2 b2 = *(const float2*)(bias + n);
                    vx += b2.x; vy += b2.y;
                }

                if (EPI == 1) {
                    vx = vx / (1.f + expf(-vx));
                    vy = vy / (1.f + expf(-vy));
                } else if (EPI == 2) {
                    vx = tanhf(vx);
                    vy = tanhf(vy);
                } else if (EPI == 3) {
                    float2 a2 = *(const float2*)(aux + (size_t)m * N + n);
                    float li0 = __ldg(lin + n),     li1 = __ldg(lin + n + 1);
                    float p30 = __ldg(gp + (size_t)n * 6 + 3), p31 = __ldg(gp + (size_t)(n + 1) * 6 + 3);
                    float p40 = __ldg(gp + (size_t)n * 6 + 4), p41 = __ldg(gp + (size_t)(n + 1) * 6 + 4);
                    float p50 = __ldg(gp + (size_t)n * 6 + 5), p51 = __ldg(gp + (size_t)(n + 1) * 6 + 5);
                    float g0 = 0.25f * (li0 * a2.x + 0.5f * sinf(p30 * a2.x + p40) + 0.5f * cosf(p50 * a2.x));
                    float g1 = 0.25f * (li1 * a2.y + 0.5f * sinf(p31 * a2.y + p41) + 0.5f * cosf(p51 * a2.y));
                    vx = (a2.x + 0.3f * g0 + 0.2f * vx) * (1.f / 1.5f);
                    vy = (a2.y + 0.3f * g1 + 0.2f * vy) * (1.f / 1.5f);
                } else if (EPI == 4) {
                    float2 a2 = *(const float2*)(aux + (size_t)m * N + n);
                    vx = a2.x + 0.1f * vx;
                    vy = a2.y + 0.1f * vy;
                }

                if (WF32) {
                    *(float2*)(outf + (size_t)m * N + n) = make_float2(vx, vy);
                }
                if (WSPLIT) {
                    bf162 lo;
                    bf162 hi = split_hi2(vx, vy, lo);
                    *(bf162*)(outh + (size_t)m * N + n) = hi;
                    *(bf162*)(outl + (size_t)m * N + n) = lo;
                }
            }
        }
    }
}

// ======================= weight prep (transpose + split + optional tanh) =======================
struct WMeta { const float* src; long long dst; int ldsrc; int K; int N; int op; };
struct WTable { WMeta m[32]; int count; long long total; };

__global__ void wprep_kernel(WTable tb) {
    long long t = (long long)blockIdx.x * blockDim.x + threadIdx.x;
    if (t >= tb.total) return;
    int d = 0;
    long long local = t;
    for (; d < tb.count; d++) {
        long long sz = (long long)tb.m[d].K * tb.m[d].N;
        if (local < sz) break;
        local -= sz;
    }
    const WMeta& w = tb.m[d];
    int n = (int)(local / w.K);
    int k = (int)(local % w.K);
    float v = w.src[(size_t)k * w.ldsrc + n];
    if (w.op) v = tanhf(v);
    bf16 h = __float2bfloat16(v);
    bf16 l = __float2bfloat16(v - __bfloat162float(h));
    g_wh[w.dst + local] = h;
    g_wl[w.dst + local] = l;
}

// ======================= x split + lin precompute =======================
__global__ void prep2_kernel(const float* __restrict__ x, const float* __restrict__ gp) {
    size_t i = (size_t)blockIdx.x * blockDim.x + threadIdx.x;
    if (i < (size_t)BATCH * 64) {
        float4 v = ((const float4*)x)[i];
        bf162 l0, l1;
        bf162 h0 = split_hi2(v.x, v.y, l0);
        bf162 h1 = split_hi2(v.z, v.w, l1);
        ((bf162*)g_xh)[i * 2]     = h0;
        ((bf162*)g_xh)[i * 2 + 1] = h1;
        ((bf162*)g_xl)[i * 2]     = l0;
        ((bf162*)g_xl)[i * 2 + 1] = l1;
    }
    if (i < 8 * NQ) {
        const float* p = gp + i * 6;
        g_lin[i] = sinf(p[0]) + cosf(p[1]) + tanhf(p[2]);
    }
}

// ======================= LayerNorm(768) + GELU -> bf16 hi/lo =======================
__global__ __launch_bounds__(256) void lngelu_kernel(const float* __restrict__ h,
                                                     const float* __restrict__ w,
                                                     const float* __restrict__ b,
                                                     bf16* __restrict__ oh,
                                                     bf16* __restrict__ ol) {
    __shared__ float red[8];
    __shared__ float bc;
    const int row = blockIdx.x;
    const int tid = threadIdx.x;
    const float* hr = h + (size_t)row * 768;

    float v[3];
    v[0] = hr[tid]; v[1] = hr[tid + 256]; v[2] = hr[tid + 512];

    float s = v[0] + v[1] + v[2];
    {
        int lane = tid & 31, wd = tid >> 5;
#pragma unroll
        for (int o = 16; o > 0; o >>= 1) s += __shfl_xor_sync(0xffffffffu, s, o);
        if (lane == 0) red[wd] = s;
        __syncthreads();
        if (tid < 8) {
            float t = red[tid];
#pragma unroll
            for (int o = 4; o > 0; o >>= 1) t += __shfl_xor_sync(0xffu, t, o);
            if (tid == 0) bc = t;
        }
        __syncthreads();
    }
    float mu = bc * (1.f / 768.f);
    __syncthreads();

    float d0 = v[0] - mu, d1 = v[1] - mu, d2 = v[2] - mu;
    float ss = d0 * d0 + d1 * d1 + d2 * d2;
    {
        int lane = tid & 31, wd = tid >> 5;
#pragma unroll
        for (int o = 16; o > 0; o >>= 1) ss += __shfl_xor_sync(0xffffffffu, ss, o);
        if (lane == 0) red[wd] = ss;
        __syncthreads();
        if (tid < 8) {
            float t = red[tid];
#pragma unroll
            for (int o = 4; o > 0; o >>= 1) t += __shfl_xor_sync(0xffu, t, o);
            if (tid == 0) bc = t;
        }
        __syncthreads();
    }
    float inv = rsqrtf(bc * (1.f / 768.f) + 1e-5f);

#pragma unroll
    for (int e = 0; e < 3; e++) {
        int c = tid + e * 256;
        float o = (v[e] - mu) * inv * w[c] + b[c];
        float g = 0.5f * o * (1.f + erff(o * 0.70710678118654752f));
        bf16 hh = __float2bfloat16(g);
        oh[(size_t)row * 768 + c] = hh;
        ol[(size_t)row * 768 + c] = __float2bfloat16(g - __bfloat162float(hh));
    }
}

// ======================= residual mix + L2 norm + tanh =======================
__global__ __launch_bounds__(256) void mix_kernel(const float* __restrict__ c3,
                                                  const float* __restrict__ res,
                                                  float* __restrict__ outf,
                                                  bf16* __restrict__ outh,
                                                  bf16* __restrict__ outl,
                                                  float alpha, int wsplit) {
    const int warp = threadIdx.x >> 5;
    const int lane = threadIdx.x & 31;
    const int row  = blockIdx.x * 8 + warp;
    const float beta = 1.f - alpha;

    const float4* c4 = (const float4*)(c3  + (size_t)row * NQ);
    const float4* r4 = (const float4*)(res + (size_t)row * NQ);

    float4 m[2];
    float ss = 0.f;
#pragma unroll
    for (int t = 0; t < 2; t++) {
        int idx = lane + t * 32;
        float4 a = c4[idx];
        float4 b = r4[idx];
        float4 mm;
        mm.x = alpha * a.x + beta * b.x;
        mm.y = alpha * a.y + beta * b.y;
        mm.z = alpha * a.z + beta * b.z;
        mm.w = alpha * a.w + beta * b.w;
        ss += mm.x * mm.x + mm.y * mm.y + mm.z * mm.z + mm.w * mm.w;
        m[t] = mm;
    }
#pragma unroll
    for (int o = 16; o > 0; o >>= 1) ss += __shfl_xor_sync(0xffffffffu, ss, o);
    float inv = 1.f / (sqrtf(ss) + 1e-8f);

#pragma unroll
    for (int t = 0; t < 2; t++) {
        int idx = lane + t * 32;
        float4 mm = m[t];
        float4 oo;
        oo.x = tanhf(mm.x * inv);
        oo.y = tanhf(mm.y * inv);
        oo.z = tanhf(mm.z * inv);
        oo.w = tanhf(mm.w * inv);
        ((float4*)(outf + (size_t)row * NQ))[idx] = oo;
        if (wsplit) {
            bf162 l0, l1;
            bf162 h0 = split_hi2(oo.x, oo.y, l0);
            bf162 h1 = split_hi2(oo.z, oo.w, l1);
            ((bf162*)(outh + (size_t)row * NQ))[idx * 2]     = h0;
            ((bf162*)(outh + (size_t)row * NQ))[idx * 2 + 1] = h1;
            ((bf162*)(outl + (size_t)row * NQ))[idx * 2]     = l0;
            ((bf162*)(outl + (size_t)row * NQ))[idx * 2 + 1] = l1;
        }
    }
}

// ======================= host =======================
template <int EPI, int WF32, int WSPLIT>
static void launchG(const bf16* Ah, const bf16* Al, size_t woff,
                    const float* bias, float* outf, bf16* outh, bf16* outl,
                    const float* aux, const float* gp, const float* lin,
                    int K, int N, bf16* wh, bf16* wl) {
    cudaFuncSetAttribute(gemm_mma<EPI, WF32, WSPLIT>,
                         cudaFuncAttributeMaxDynamicSharedMemorySize, SMEM_BYTES);
    dim3 grid(N / 128, BATCH / 128);
    gemm_mma<EPI, WF32, WSPLIT><<<grid, 256, SMEM_BYTES>>>(
        Ah, Al, wh + woff, wl + woff, bias, outf, outh, outl, aux, gp, lin, K, N);
}

extern "C" void kernel_launch(void* const* d_in, const int* in_sizes, int n_in,
                              void* d_out, int out_size) {
    const float* x     = (const float*)d_in[0];
    const float* d0w1  = (const float*)d_in[1];
    const float* d0b1  = (const float*)d_in[2];
    const float* lnw   = (const float*)d_in[3];
    const float* lnb   = (const float*)d_in[4];
    const float* d0w2  = (const float*)d_in[5];
    const float* d0b2  = (const float*)d_in[6];
    const float* d1w1  = (const float*)d_in[7];
    const float* d1b1  = (const float*)d_in[8];
    const float* d1w2  = (const float*)d_in[9];
    const float* d1b2  = (const float*)d_in[10];
    const float* awqkv = (const float*)d_in[11];
    const float* abqkv = (const float*)d_in[12];
    const float* awo   = (const float*)d_in[13];
    const float* abo   = (const float*)d_in[14];
    const float* gp    = (const float*)d_in[15];
    const float* ent   = (const float*)d_in[16];
    const float* nlw1  = (const float*)d_in[17];
    const float* nlb1  = (const float*)d_in[18];
    const float* nlw2  = (const float*)d_in[19];
    const float* nlb2  = (const float*)d_in[20];

    float *bufA, *bufB, *hf, *t2, *t3, *lin;
    bf16 *xh, *xl, *Ah, *Al, *Bh, *Bl, *hh, *hl, *t2h, *t2l, *t3h, *t3l, *wh, *wl;
    cudaGetSymbolAddress((void**)&bufA, g_bufA);
    cudaGetSymbolAddress((void**)&bufB, g_bufB);
    cudaGetSymbolAddress((void**)&hf,   g_h);
    cudaGetSymbolAddress((void**)&t2,   g_t2);
    cudaGetSymbolAddress((void**)&t3,   g_t3);
    cudaGetSymbolAddress((void**)&lin,  g_lin);
    cudaGetSymbolAddress((void**)&xh,   g_xh);
    cudaGetSymbolAddress((void**)&xl,   g_xl);
    cudaGetSymbolAddress((void**)&Ah,   g_Ah);
    cudaGetSymbolAddress((void**)&Al,   g_Al);
    cudaGetSymbolAddress((void**)&Bh,   g_Bh2);
    cudaGetSymbolAddress((void**)&Bl,   g_Bl2);
    cudaGetSymbolAddress((void**)&hh,   g_hh);
    cudaGetSymbolAddress((void**)&hl,   g_hl);
    cudaGetSymbolAddress((void**)&t2h,  g_t2h);
    cudaGetSymbolAddress((void**)&t2l,  g_t2l);
    cudaGetSymbolAddress((void**)&t3h,  g_t3h);
    cudaGetSymbolAddress((void**)&t3l,  g_t3l);
    cudaGetSymbolAddress((void**)&wh,   g_wh);
    cudaGetSymbolAddress((void**)&wl,   g_wl);

    // ---- build weight table (dst layout: [N][K], k contiguous) ----
    WTable tb;
    long long off = 0;
    int c = 0;
    size_t o_d0w1[3], o_d0w2[3], o_d1w1[3], o_d1w2[3], o_av[2], o_wo[2], o_ent[8], o_n1[4], o_n2[4];
    for (int i = 0; i < 3; i++) { o_d0w1[i] = off; tb.m[c++] = {d0w1 + (size_t)i * 256 * 768, off, 768, 256, 768, 0}; off += 256LL * 768; }
    for (int i = 0; i < 3; i++) { o_d0w2[i] = off; tb.m[c++] = {d0w2 + (size_t)i * 768 * 256, off, 256, 768, 256, 0}; off += 768LL * 256; }
    for (int i = 0; i < 3; i++) { o_d1w1[i] = off; tb.m[c++] = {d1w1 + (size_t)i * 256 * 512, off, 512, 256, 512, 0}; off += 256LL * 512; }
    for (int i = 0; i < 3; i++) { o_d1w2[i] = off; tb.m[c++] = {d1w2 + (size_t)i * 512 * 256, off, 256, 512, 256, 0}; off += 512LL * 256; }
    for (int i = 0; i < 2; i++) { o_av[i]   = off; tb.m[c++] = {awqkv + (size_t)i * 256 * 768 + 512, off, 768, 256, 256, 0}; off += 256LL * 256; }
    for (int i = 0; i < 2; i++) { o_wo[i]   = off; tb.m[c++] = {awo + (size_t)i * 256 * 256, off, 256, 256, 256, 0}; off += 256LL * 256; }
    for (int i = 0; i < 8; i++) { o_ent[i]  = off; tb.m[c++] = {ent + (size_t)i * 256 * 256, off, 256, 256, 256, 1}; off += 256LL * 256; }
    for (int i = 0; i < 4; i++) { o_n1[i]   = off; tb.m[c++] = {nlw1 + (size_t)i * 256 * 256, off, 256, 256, 256, 0}; off += 256LL * 256; }
    for (int i = 0; i < 4; i++) { o_n2[i]   = off; tb.m[c++] = {nlw2 + (size_t)i * 256 * 256, off, 256, 256, 256, 0}; off += 256LL * 256; }
    tb.count = c;
    tb.total = off;

    wprep_kernel<<<(unsigned)((off + 255) / 256), 256>>>(tb);
    prep2_kernel<<<(BATCH * 64 + 255) / 256, 256>>>(x, gp);

    const float* curf = x;
    const bf16* curh = xh;
    const bf16* curl = xl;

    for (int li = 0; li < 8; li++) {
        float* nxtf = (li == 7) ? (float*)d_out : ((li & 1) ? bufB : bufA);
        bf16* nxth = (li & 1) ? Bh : Ah;
        bf16* nxtl = (li & 1) ? Bl : Al;
        int t = li % 3;
        if (t == 0) {
            int i = li / 3;
            launchG<0,1,0>(curh, curl, o_d0w1[i], d0b1 + (size_t)i * 768, hf, nullptr, nullptr,
                           nullptr, nullptr, nullptr, 256, 768, wh, wl);
            lngelu_kernel<<<BATCH, 256>>>(hf, lnw + (size_t)i * 768, lnb + (size_t)i * 768, hh, hl);
            launchG<0,1,1>(hh, hl, o_d0w2[i], d0b2 + (size_t)i * 256, t2, t2h, t2l,
                           nullptr, nullptr, nullptr, 768, 256, wh, wl);
        } else if (t == 1) {
            int i = (li - 1) / 3;
            launchG<1,0,1>(curh, curl, o_d1w1[i], d1b1 + (size_t)i * 512, nullptr, hh, hl,
                           nullptr, nullptr, nullptr, 256, 512, wh, wl);
            launchG<0,1,1>(hh, hl, o_d1w2[i], d1b2 + (size_t)i * 256, t2, t2h, t2l,
                           nullptr, nullptr, nullptr, 512, 256, wh, wl);
        } else {
            int i = (li - 2) / 3;
            launchG<0,0,1>(curh, curl, o_av[i], abqkv + (size_t)i * 768 + 512, nullptr, t3h, t3l,
                           nullptr, nullptr, nullptr, 256, 256, wh, wl);
            launchG<0,1,1>(t3h, t3l, o_wo[i], abo + (size_t)i * 256, t2, t2h, t2l,
                           nullptr, nullptr, nullptr, 256, 256, wh, wl);
        }

        // entangle + gate fusion: t3 = combine(t2, t2 @ tanh(ent))
        launchG<3,1,1>(t2h, t2l, o_ent[li], nullptr, t3, t3h, t3l,
                       t2, gp + (size_t)li * 256 * 6, lin + (size_t)li * 256, 256, 256, wh, wl);

        const float* c3 = t3;
        if (li & 1) {
            int j = li / 2;
            launchG<2,0,1>(t3h, t3l, o_n1[j], nlb1 + (size_t)j * 256, nullptr, hh, hl,
                           nullptr, nullptr, nullptr, 256, 256, wh, wl);
            launchG<4,1,0>(hh, hl, o_n2[j], nlb2 + (size_t)j * 256, t2, nullptr, nullptr,
                           t3, nullptr, nullptr, 256, 256, wh, wl);
            c3 = t2;
        }

        float alpha = (li < 4) ? 0.8f : 0.6f;
        mix_kernel<<<BATCH / 8, 256>>>(c3, curf, nxtf, nxth, nxtl, alpha, (li == 7) ? 0 : 1);
        curf = nxtf; curh = nxth; curl = nxtl;
    }
}